// round 10
// baseline (speedup 1.0000x reference)
#include <cuda_runtime.h>

// ---------------------------------------------------------------------------
// DNN_SKalmanNet_GSS — batch-1 GEMV chain, HBM-bound (~499 MB weights/pass).
// 4 launches, R1-proven inner loop + once-only overhead elimination:
//   K1: input built in smem + l1/l3 GEMV (relu)           [~46 MB]  640x2
//   K2: GRU gi/gh GEMV 4 segs + LAST-BLOCK gate finalize  [~352 MB] 768x4
//       (gate computed exactly once, on the tail of K2)
//   K3: W1 GEMV (relu) + output-bias prewrite             [~67 MB]  512x2
//   K4: W2 GEMV split-K x4, atomicAdd into d_out          [~34 MB]  128x8
// ---------------------------------------------------------------------------

#define H1   5120
#define H2   4096
#define HID  2048
#define IN1  1120

__device__ float g_l1[H1];
__device__ float g_l3[H1];
__device__ float g_gi1[3 * HID];
__device__ float g_gh1[3 * HID];
__device__ float g_gi2[3 * HID];
__device__ float g_gh2[3 * HID];
__device__ float g_h1[HID];
__device__ float g_h2[HID];
__device__ float g_hid1[H2];
__device__ float g_hid2[H2];
__device__ unsigned int g_k2done;   // zero-init; reset by last block each run

// R1-proven warp-per-row GEMV; x staged in smem as float4.
__device__ __forceinline__ void gemv_core(const float* __restrict__ W,
                                          const float* __restrict__ b,
                                          float* __restrict__ y,
                                          int rows, int c4, int act,
                                          const float4* __restrict__ sx) {
    const int lane = threadIdx.x & 31;
    const int warp = (blockIdx.x * blockDim.x + threadIdx.x) >> 5;
    const int nw   = (gridDim.x * blockDim.x) >> 5;
    for (int row = warp; row < rows; row += nw) {
        const float4* __restrict__ Wr = (const float4*)W + (size_t)row * c4;
        float acc = 0.f;
        #pragma unroll 4
        for (int j = lane; j < c4; j += 32) {
            float4 w = Wr[j];
            float4 x = sx[j];
            acc = fmaf(w.x, x.x, acc);
            acc = fmaf(w.y, x.y, acc);
            acc = fmaf(w.z, x.z, acc);
            acc = fmaf(w.w, x.w, acc);
        }
        #pragma unroll
        for (int o = 16; o; o >>= 1) acc += __shfl_xor_sync(0xffffffffu, acc, o);
        if (lane == 0) {
            float v = acc + b[row];
            if (act) v = fmaxf(v, 0.f);
            y[row] = v;
        }
    }
}

extern __shared__ float4 smem_x[];

// K1: build branch input in smem, then l1/l3 GEMV (relu). blockIdx.y = branch.
__global__ void k1_input_gemv(const float* __restrict__ si,
                              const float* __restrict__ oi,
                              const float* __restrict__ ds,
                              const float* __restrict__ dob,
                              const float* __restrict__ le,
                              const float* __restrict__ J,
                              const float* __restrict__ l1W,
                              const float* __restrict__ l1b,
                              const float* __restrict__ l3W,
                              const float* __restrict__ l3b) {
    const int br = blockIdx.y;
    float* s = (float*)smem_x;
    for (int i = threadIdx.x; i < IN1; i += blockDim.x) {
        float v;
        if (i < 32)       v = br ? oi[i]       : si[i];
        else if (i < 64)  v = br ? dob[i - 32] : ds[i - 32];
        else if (i < 96)  v = le[i - 64];
        else              v = J[i - 96];
        s[i] = v;
    }
    __syncthreads();
    gemv_core(br ? l3W : l1W, br ? l3b : l1b, br ? g_l3 : g_l1,
              H1, IN1 / 4, 1, smem_x);
}

// K2: 4-segment GEMV (gi1, gh1, gi2, gh2) + last-block gate finalization.
struct Seg { const float *W, *x, *b; float* y; int c4; };
struct Segs4 { Seg s[4]; };

__global__ void k2_gru_gemv(Segs4 segs,
                            const float* __restrict__ hn1,
                            const float* __restrict__ hn2) {
    Seg s = segs.s[blockIdx.y];
    const float4* __restrict__ xv = (const float4*)s.x;
    for (int j = threadIdx.x; j < s.c4; j += blockDim.x) smem_x[j] = xv[j];
    __syncthreads();
    gemv_core(s.W, s.b, s.y, 3 * HID, s.c4, 0, smem_x);

    // --- last-block gate finalization (gates computed exactly once) ---
    __threadfence();                      // publish this block's gi/gh writes
    __shared__ bool amLast;
    if (threadIdx.x == 0) {
        unsigned total = gridDim.x * gridDim.y;
        unsigned old = atomicAdd(&g_k2done, 1u);
        amLast = (old == total - 1u);
    }
    __syncthreads();
    if (amLast) {
        if (threadIdx.x == 0) g_k2done = 0u;   // reset for next graph replay
        __threadfence();                       // acquire all blocks' writes
        for (int i = threadIdx.x; i < 2 * HID; i += blockDim.x) {
            const int br = (i >= HID);
            const int k  = i - br * HID;
            const float* gi = br ? g_gi2 : g_gi1;
            const float* gh = br ? g_gh2 : g_gh1;
            const float* hp = br ? hn2 : hn1;
            float*       h  = br ? g_h2 : g_h1;
            float r = 1.f / (1.f + __expf(-(gi[k]       + gh[k])));
            float z = 1.f / (1.f + __expf(-(gi[k + HID] + gh[k + HID])));
            float n = tanhf(gi[k + 2 * HID] + r * gh[k + 2 * HID]);
            h[k] = (1.f - z) * n + z * hp[k];
        }
    }
}

// K3: hidden = relu(W1 @ h + b1); block 0 of each branch pre-writes the
// output bias b2 into d_out so K4 can atomicAdd split-K partials on top.
__global__ void k3_hidden_gemv(const float* __restrict__ l2W1,
                               const float* __restrict__ l2b1,
                               const float* __restrict__ l4W1,
                               const float* __restrict__ l4b1,
                               const float* __restrict__ l2b2,
                               const float* __restrict__ l4b2,
                               float* __restrict__ out) {
    const int br = blockIdx.y;
    if (blockIdx.x == 0) {
        const float* b2 = br ? l4b2 : l2b2;
        for (int i = threadIdx.x; i < 1024; i += blockDim.x)
            out[br * 1024 + i] = b2[i];
    }
    const float* __restrict__ h = br ? g_h2 : g_h1;
    const float4* __restrict__ xv = (const float4*)h;
    for (int j = threadIdx.x; j < HID / 4; j += blockDim.x) smem_x[j] = xv[j];
    __syncthreads();
    gemv_core(br ? l4W1 : l2W1, br ? l4b1 : l2b1, br ? g_hid2 : g_hid1,
              H2, HID / 4, 1, smem_x);
}

// K4: split-K x4 output GEMV. y in [0,8): br = y>>2, chunk q = y&3.
// Each block: 8 warps, 8 rows, 1024-col partial dot -> atomicAdd into out.
#define CHUNK4 (H2 / 4 / 4)   // 256 float4 per chunk

__global__ void k4_out_gemv(const float* __restrict__ l2W2,
                            const float* __restrict__ l4W2,
                            float* __restrict__ out) {
    const int br = blockIdx.y >> 2;
    const int q  = blockIdx.y & 3;
    const float* __restrict__ W = br ? l4W2 : l2W2;
    const float* __restrict__ x = br ? g_hid2 : g_hid1;

    const float4* __restrict__ xv = (const float4*)x + q * CHUNK4;
    for (int j = threadIdx.x; j < CHUNK4; j += blockDim.x) smem_x[j] = xv[j];
    __syncthreads();

    const int lane = threadIdx.x & 31;
    const int row  = blockIdx.x * 8 + (threadIdx.x >> 5);   // 128 blocks * 8
    const float4* __restrict__ Wr =
        (const float4*)W + (size_t)row * (H2 / 4) + q * CHUNK4;
    float acc = 0.f;
    #pragma unroll 4
    for (int j = lane; j < CHUNK4; j += 32) {
        float4 w  = Wr[j];
        float4 xx = smem_x[j];
        acc = fmaf(w.x, xx.x, acc);
        acc = fmaf(w.y, xx.y, acc);
        acc = fmaf(w.z, xx.z, acc);
        acc = fmaf(w.w, xx.w, acc);
    }
    #pragma unroll
    for (int o = 16; o; o >>= 1) acc += __shfl_xor_sync(0xffffffffu, acc, o);
    if (lane == 0) atomicAdd(&out[br * 1024 + row], acc);
}

extern "C" void kernel_launch(void* const* d_in, const int* in_sizes, int n_in,
                              void* d_out, int out_size) {
    const float* si    = (const float*)d_in[0];
    const float* oi    = (const float*)d_in[1];
    const float* ds    = (const float*)d_in[2];
    const float* dob   = (const float*)d_in[3];
    const float* le    = (const float*)d_in[4];
    const float* J     = (const float*)d_in[5];
    const float* l1W   = (const float*)d_in[6];
    const float* l1b   = (const float*)d_in[7];
    const float* g1Wih = (const float*)d_in[8];
    const float* g1Whh = (const float*)d_in[9];
    const float* g1bih = (const float*)d_in[10];
    const float* g1bhh = (const float*)d_in[11];
    const float* l2W1  = (const float*)d_in[12];
    const float* l2b1  = (const float*)d_in[13];
    const float* l2W2  = (const float*)d_in[14];
    const float* l2b2  = (const float*)d_in[15];
    const float* l3W   = (const float*)d_in[16];
    const float* l3b   = (const float*)d_in[17];
    const float* g2Wih = (const float*)d_in[18];
    const float* g2Whh = (const float*)d_in[19];
    const float* g2bih = (const float*)d_in[20];
    const float* g2bhh = (const float*)d_in[21];
    const float* l4W1  = (const float*)d_in[22];
    const float* l4b1  = (const float*)d_in[23];
    const float* l4W2  = (const float*)d_in[24];
    const float* l4b2  = (const float*)d_in[25];
    const float* hn1   = (const float*)d_in[26];
    const float* hn2   = (const float*)d_in[27];
    float* out = (float*)d_out;

    float *p_l1, *p_l3, *p_gi1, *p_gh1, *p_gi2, *p_gh2;
    cudaGetSymbolAddress((void**)&p_l1,  g_l1);
    cudaGetSymbolAddress((void**)&p_l3,  g_l3);
    cudaGetSymbolAddress((void**)&p_gi1, g_gi1);
    cudaGetSymbolAddress((void**)&p_gh1, g_gh1);
    cudaGetSymbolAddress((void**)&p_gi2, g_gi2);
    cudaGetSymbolAddress((void**)&p_gh2, g_gh2);

    // K1: 5120 rows / 8 warps -> 640 blocks x 2 branches, smem 4.4 KB
    k1_input_gemv<<<dim3(H1 / 8, 2), 256, IN1 * sizeof(float)>>>(
        si, oi, ds, dob, le, J, l1W, l1b, l3W, l3b);

    // K2: 6144 rows / 8 warps -> 768 blocks x 4 segments, smem 20 KB
    {
        Segs4 sg;
        sg.s[0] = { g1Wih, p_l1, g1bih, p_gi1, H1 / 4 };
        sg.s[1] = { g1Whh, hn1,  g1bhh, p_gh1, HID / 4 };
        sg.s[2] = { g2Wih, p_l3, g2bih, p_gi2, H1 / 4 };
        sg.s[3] = { g2Whh, hn2,  g2bhh, p_gh2, HID / 4 };
        k2_gru_gemv<<<dim3((3 * HID) / 8, 4), 256, H1 * sizeof(float)>>>(
            sg, hn1, hn2);
    }

    // K3: 4096 rows / 8 warps -> 512 blocks x 2 branches, smem 8 KB
    k3_hidden_gemv<<<dim3(H2 / 8, 2), 256, HID * sizeof(float)>>>(
        l2W1, l2b1, l4W1, l4b1, l2b2, l4b2, out);

    // K4: 128 blocks x (2 branches * 4 chunks), smem 4 KB
    k4_out_gemv<<<dim3(128, 8), 256, CHUNK4 * sizeof(float4)>>>(
        l2W2, l4W2, out);

    (void)in_sizes; (void)n_in; (void)out_size;
}

// round 12
// speedup vs baseline: 1.1965x; 1.1965x over previous
#include <cuda_runtime.h>

// ---------------------------------------------------------------------------
// DNN_SKalmanNet_GSS — single persistent kernel v2 (high occupancy).
// No dynamic smem: x vectors read via L1-cached global loads (shared by all
// warps in a block). 6 blocks/SM (vs 2 in v1) -> occ ~75%.
// Phases (grid barrier between):
//   P1: input built in 4.5KB static smem + l1/l3 GEMV (relu)   [~46 MB]
//   P2: GRU gi/gh GEMV, 4 byte-weighted segments               [~352 MB]
//   G : gate (16 blocks) + output-bias prewrite (2 blocks)
//   P3: W1 GEMV (relu)                                         [~67 MB]
//   P4: W2 GEMV split-K x4, atomicAdd -> d_out                 [~34 MB]
// ---------------------------------------------------------------------------

#define H1   5120
#define H2   4096
#define HID  2048
#define IN1  1120

__device__ float g_l1[H1];
__device__ float g_l3[H1];
__device__ float g_gi1[3 * HID];
__device__ float g_gh1[3 * HID];
__device__ float g_gi2[3 * HID];
__device__ float g_gh2[3 * HID];
__device__ float g_h1[HID];
__device__ float g_h2[HID];
__device__ float g_hid1[H2];
__device__ float g_hid2[H2];

__device__ unsigned int g_bar_cnt;   // zero-init, self-resetting
__device__ unsigned int g_bar_gen;   // monotonically increasing

struct Params {
    const float *si, *oi, *ds, *dob, *le, *J;
    const float *l1W, *l1b, *g1Wih, *g1Whh, *g1bih, *g1bhh;
    const float *l2W1, *l2b1, *l2W2, *l2b2;
    const float *l3W, *l3b, *g2Wih, *g2Whh, *g2bih, *g2bhh;
    const float *l4W1, *l4b1, *l4W2, *l4b2;
    const float *hn1, *hn2;
    float* out;
    int nblk, p2s1, p2s2, p2s3;
};

__device__ __forceinline__ void grid_bar(int nblk) {
    __syncthreads();
    if (threadIdx.x == 0) {
        unsigned gen = *(volatile unsigned*)&g_bar_gen;
        __threadfence();
        unsigned old = atomicAdd(&g_bar_cnt, 1u);
        if (old == (unsigned)nblk - 1u) {
            g_bar_cnt = 0u;
            __threadfence();
            *(volatile unsigned*)&g_bar_gen = gen + 1u;
        } else {
            while (*(volatile unsigned*)&g_bar_gen == gen) __nanosleep(32);
        }
        __threadfence();
    }
    __syncthreads();
}

// Warp-per-row GEMV; x via generic pointer (smem or L1-cached global).
__device__ __forceinline__ void gemv_seg(const float* __restrict__ W,
                                         const float* __restrict__ b,
                                         float* __restrict__ y,
                                         int rows, int c4, int act,
                                         const float4* __restrict__ xv,
                                         int blkRank, int nblkSeg) {
    const int lane = threadIdx.x & 31;
    const int nw   = nblkSeg << 3;                    // 8 warps/block
    int w = (blkRank << 3) + (threadIdx.x >> 5);
    for (int row = w; row < rows; row += nw) {
        const float4* __restrict__ Wr = (const float4*)W + (size_t)row * c4;
        float acc = 0.f;
        #pragma unroll 4
        for (int j = lane; j < c4; j += 32) {
            float4 wv = Wr[j];
            float4 x  = xv[j];
            acc = fmaf(wv.x, x.x, acc);
            acc = fmaf(wv.y, x.y, acc);
            acc = fmaf(wv.z, x.z, acc);
            acc = fmaf(wv.w, x.w, acc);
        }
        #pragma unroll
        for (int o = 16; o; o >>= 1) acc += __shfl_xor_sync(0xffffffffu, acc, o);
        if (lane == 0) {
            float v = acc + b[row];
            if (act) v = fmaxf(v, 0.f);
            y[row] = v;
        }
    }
}

__global__ __launch_bounds__(256, 6) void skn2(Params p) {
    __shared__ float s_in[IN1];
    const int blk  = blockIdx.x;
    const int half = p.nblk >> 1;

    // ---- P1: build input in smem, l1/l3 GEMV (relu) ----
    {
        const int seg  = (blk >= half) ? 1 : 0;
        const int rank = seg ? blk - half : blk;
        const int nb   = seg ? p.nblk - half : half;
        for (int i = threadIdx.x; i < IN1; i += blockDim.x) {
            float v;
            if (i < 32)       v = seg ? p.oi[i]       : p.si[i];
            else if (i < 64)  v = seg ? p.dob[i - 32] : p.ds[i - 32];
            else if (i < 96)  v = p.le[i - 64];
            else              v = p.J[i - 96];
            s_in[i] = v;
        }
        __syncthreads();
        gemv_seg(seg ? p.l3W : p.l1W, seg ? p.l3b : p.l1b,
                 seg ? g_l3 : g_l1, H1, IN1 / 4, 1,
                 (const float4*)s_in, rank, nb);
    }
    grid_bar(p.nblk);

    // ---- P2: GRU pre-gates, 4 byte-weighted segments (x via L1) ----
    {
        const float *W, *xx, *b; float* y; int c4, start, nb;
        if (blk < p.p2s1)      { W = p.g1Wih; xx = g_l1;  b = p.g1bih; y = g_gi1; c4 = H1 / 4;  start = 0;      nb = p.p2s1;          }
        else if (blk < p.p2s2) { W = p.g1Whh; xx = p.hn1; b = p.g1bhh; y = g_gh1; c4 = HID / 4; start = p.p2s1; nb = p.p2s2 - p.p2s1; }
        else if (blk < p.p2s3) { W = p.g2Wih; xx = g_l3;  b = p.g2bih; y = g_gi2; c4 = H1 / 4;  start = p.p2s2; nb = p.p2s3 - p.p2s2; }
        else                   { W = p.g2Whh; xx = p.hn2; b = p.g2bhh; y = g_gh2; c4 = HID / 4; start = p.p2s3; nb = p.nblk - p.p2s3; }
        gemv_seg(W, b, y, 3 * HID, c4, 0, (const float4*)xx, blk - start, nb);
    }
    grid_bar(p.nblk);

    // ---- G: gate (blocks 0..15) + bias prewrite (blocks 16,17) ----
    if (blk < 16) {
        const int i = (blk << 8) + threadIdx.x;      // 16*256 = 4096
        const int br = (i >= HID);
        const int k  = i - br * HID;
        const float* gi = br ? g_gi2 : g_gi1;
        const float* gh = br ? g_gh2 : g_gh1;
        const float* hp = br ? p.hn2 : p.hn1;
        float*       h  = br ? g_h2 : g_h1;
        float r = 1.f / (1.f + __expf(-(gi[k]       + gh[k])));
        float z = 1.f / (1.f + __expf(-(gi[k + HID] + gh[k + HID])));
        float n = tanhf(gi[k + 2 * HID] + r * gh[k + 2 * HID]);
        h[k] = (1.f - z) * n + z * hp[k];
    } else if (blk < 18) {
        const int br = blk - 16;
        const float* b2 = br ? p.l4b2 : p.l2b2;
        for (int i = threadIdx.x; i < 1024; i += blockDim.x)
            p.out[br * 1024 + i] = b2[i];
    }
    grid_bar(p.nblk);

    // ---- P3: hidden = relu(W1 @ h + b1) ----
    {
        const int seg  = (blk >= half) ? 1 : 0;
        const int rank = seg ? blk - half : blk;
        const int nb   = seg ? p.nblk - half : half;
        gemv_seg(seg ? p.l4W1 : p.l2W1, seg ? p.l4b1 : p.l2b1,
                 seg ? g_hid2 : g_hid1, H2, HID / 4, 1,
                 (const float4*)(seg ? g_h2 : g_h1), rank, nb);
    }
    grid_bar(p.nblk);

    // ---- P4: out += W2 @ hidden (split-K x4, atomics; bias pre-written) ----
    {
        const int totw = p.nblk << 3;
        const int gw   = (blk << 3) + (threadIdx.x >> 5);
        const int lane = threadIdx.x & 31;
        // 8192 tasks: t -> br = t>>12, row = (t&4095)>>2, chunk q = t&3
        for (int t = gw; t < 8192; t += totw) {
            const int br  = t >> 12;
            const int row = (t & 4095) >> 2;
            const int q   = t & 3;
            const float* __restrict__ W = br ? p.l4W2 : p.l2W2;
            const float4* __restrict__ xv =
                (const float4*)(br ? g_hid2 : g_hid1) + q * 256;
            const float4* __restrict__ Wr =
                (const float4*)W + (size_t)row * (H2 / 4) + q * 256;
            float acc = 0.f;
            #pragma unroll 4
            for (int j = lane; j < 256; j += 32) {
                float4 w = Wr[j];
                float4 x = xv[j];
                acc = fmaf(w.x, x.x, acc);
                acc = fmaf(w.y, x.y, acc);
                acc = fmaf(w.z, x.z, acc);
                acc = fmaf(w.w, x.w, acc);
            }
            #pragma unroll
            for (int o = 16; o; o >>= 1) acc += __shfl_xor_sync(0xffffffffu, acc, o);
            if (lane == 0) atomicAdd(&p.out[br * 1024 + row], acc);
        }
    }
}

extern "C" void kernel_launch(void* const* d_in, const int* in_sizes, int n_in,
                              void* d_out, int out_size) {
    Params p;
    p.si    = (const float*)d_in[0];
    p.oi    = (const float*)d_in[1];
    p.ds    = (const float*)d_in[2];
    p.dob   = (const float*)d_in[3];
    p.le    = (const float*)d_in[4];
    p.J     = (const float*)d_in[5];
    p.l1W   = (const float*)d_in[6];
    p.l1b   = (const float*)d_in[7];
    p.g1Wih = (const float*)d_in[8];
    p.g1Whh = (const float*)d_in[9];
    p.g1bih = (const float*)d_in[10];
    p.g1bhh = (const float*)d_in[11];
    p.l2W1  = (const float*)d_in[12];
    p.l2b1  = (const float*)d_in[13];
    p.l2W2  = (const float*)d_in[14];
    p.l2b2  = (const float*)d_in[15];
    p.l3W   = (const float*)d_in[16];
    p.l3b   = (const float*)d_in[17];
    p.g2Wih = (const float*)d_in[18];
    p.g2Whh = (const float*)d_in[19];
    p.g2bih = (const float*)d_in[20];
    p.g2bhh = (const float*)d_in[21];
    p.l4W1  = (const float*)d_in[22];
    p.l4b1  = (const float*)d_in[23];
    p.l4W2  = (const float*)d_in[24];
    p.l4b2  = (const float*)d_in[25];
    p.hn1   = (const float*)d_in[26];
    p.hn2   = (const float*)d_in[27];
    p.out   = (float*)d_out;

    int dev = 0;
    cudaGetDevice(&dev);
    int numSM = 148;
    cudaDeviceGetAttribute(&numSM, cudaDevAttrMultiProcessorCount, dev);
    int occ = 1;
    cudaOccupancyMaxActiveBlocksPerMultiprocessor(&occ, skn2, 256, 0);
    if (occ < 1) occ = 1;
    if (occ > 8) occ = 8;
    int nblk = occ * numSM;               // all co-resident -> barrier safe
    if (nblk < 32) nblk = 32;             // gate/bias blocks must exist

    p.nblk = nblk;
    int b0 = (int)((long long)nblk * 63 / 176); if (b0 < 1) b0 = 1;
    int b1 = (int)((long long)nblk * 25 / 176); if (b1 < 1) b1 = 1;
    p.p2s1 = b0;
    p.p2s2 = b0 + b1;
    p.p2s3 = b0 + b1 + b0;
    if (p.p2s3 >= nblk) p.p2s3 = nblk - 1;

    skn2<<<nblk, 256>>>(p);
    (void)in_sizes; (void)n_in; (void)out_size;
}